// round 4
// baseline (speedup 1.0000x reference)
#include <cuda_runtime.h>
#include <math.h>

// ---------------------------------------------------------------------------
// JPEG round-trip:  (32, 3, 512, 512) fp32, quality scalar.
// One CTA (192 threads) = one 8-row x 512-col strip of one image.
//   Phase A: RGB -> YCbCr-128 into SMEM (exact _rn fp32 like the JAX reference)
//   Phase B: per-thread 8x8 block (3ch x 64blk = 192): DCT -> quant -> IDCT
//   Phase C: YCbCr -> RGB, round/clip, store.
// ---------------------------------------------------------------------------

#define NB 32
#define NH 512
#define NW 512
#define QROW   132            // float4 quads per smem row: 64 + pad(4) + 64
#define PLANEQ (8 * QROW)     // 1056 quads per channel plane
#define SMEM_BYTES (3 * PLANEQ * 16 + 128 * 8)   // planes + float2 qtab[128]

static __device__ const float LUMT[64] = {
    16,11,10,16,24,40,51,61,
    12,12,14,19,26,58,60,55,
    14,13,16,24,40,57,69,56,
    14,17,22,29,51,87,80,62,
    18,22,37,56,68,109,103,77,
    24,35,55,64,81,104,113,92,
    49,64,78,87,103,121,120,101,
    72,92,95,98,112,100,103,99};
static __device__ const float CHRT[64] = {
    17,18,24,47,99,99,99,99,
    18,21,26,66,99,99,99,99,
    24,26,56,99,99,99,99,99,
    47,66,99,99,99,99,99,99,
    99,99,99,99,99,99,99,99,
    99,99,99,99,99,99,99,99,
    99,99,99,99,99,99,99,99,
    99,99,99,99,99,99,99,99};

// 0.5*cos(k*pi/16) constants (rounded from double, matches fp32(D))
#define CA  0.35355339059327373f
#define CC1 0.49039264020161522f
#define CC2 0.46193976625564337f
#define CC3 0.41573480615127262f
#define CC5 0.27778511650980114f
#define CC6 0.19134171618254492f
#define CC7 0.097545161008064166f

template <int S>
__device__ __forceinline__ void dct8(float* v) {
    float x0 = v[0 * S], x1 = v[1 * S], x2 = v[2 * S], x3 = v[3 * S];
    float x4 = v[4 * S], x5 = v[5 * S], x6 = v[6 * S], x7 = v[7 * S];
    float s0 = x0 + x7, s1 = x1 + x6, s2 = x2 + x5, s3 = x3 + x4;
    float d0 = x0 - x7, d1 = x1 - x6, d2 = x2 - x5, d3 = x3 - x4;
    float e0 = s0 + s3, e1 = s1 + s2;
    float f0 = s0 - s3, f1 = s1 - s2;
    v[0 * S] = CA * (e0 + e1);
    v[4 * S] = CA * (e0 - e1);
    v[2 * S] = fmaf(CC2, f0,  CC6 * f1);
    v[6 * S] = fmaf(CC6, f0, -(CC2 * f1));
    v[1 * S] = fmaf(CC1, d0, fmaf( CC3, d1, fmaf( CC5, d2,  CC7 * d3)));
    v[3 * S] = fmaf(CC3, d0, fmaf(-CC7, d1, fmaf(-CC1, d2, -(CC5 * d3))));
    v[5 * S] = fmaf(CC5, d0, fmaf(-CC1, d1, fmaf( CC7, d2,  CC3 * d3)));
    v[7 * S] = fmaf(CC7, d0, fmaf(-CC5, d1, fmaf( CC3, d2, -(CC1 * d3))));
}

template <int S>
__device__ __forceinline__ void idct8(float* v) {
    float x0 = v[0 * S], x1 = v[1 * S], x2 = v[2 * S], x3 = v[3 * S];
    float x4 = v[4 * S], x5 = v[5 * S], x6 = v[6 * S], x7 = v[7 * S];
    float ea = CA * (x0 + x4);
    float eb = CA * (x0 - x4);
    float ec = fmaf(CC2, x2,  CC6 * x6);
    float ed = fmaf(CC6, x2, -(CC2 * x6));
    float e0 = ea + ec, e1 = eb + ed, e2 = eb - ed, e3 = ea - ec;
    float o0 = fmaf(CC1, x1, fmaf( CC3, x3, fmaf( CC5, x5,  CC7 * x7)));
    float o1 = fmaf(CC3, x1, fmaf(-CC7, x3, fmaf(-CC1, x5, -(CC5 * x7))));
    float o2 = fmaf(CC5, x1, fmaf(-CC1, x3, fmaf( CC7, x5,  CC3 * x7)));
    float o3 = fmaf(CC7, x1, fmaf(-CC5, x3, fmaf( CC3, x5, -(CC1 * x7))));
    v[0 * S] = e0 + o0;  v[7 * S] = e0 - o0;
    v[1 * S] = e1 + o1;  v[6 * S] = e1 - o1;
    v[2 * S] = e2 + o2;  v[5 * S] = e2 - o2;
    v[3 * S] = e3 + o3;  v[4 * S] = e3 - o3;
}

__device__ __forceinline__ float to255(float x) {
    // round(clip(x,0,1)*255) bit-exact vs reference (rintf = half-even)
    return rintf(__fmul_rn(fminf(fmaxf(x, 0.0f), 1.0f), 255.0f));
}

__device__ __forceinline__ void fwd_px(float r, float g, float bl,
                                       float& y, float& cb, float& cr) {
    r = to255(r); g = to255(g); bl = to255(bl);
    // exact _rn ops, same association order as the JAX reference
    float yv = __fadd_rn(__fadd_rn(__fmul_rn(0.299f, r), __fmul_rn(0.587f, g)),
                         __fmul_rn(0.114f, bl));
    float cbv = __fadd_rn(__fadd_rn(__fsub_rn(__fmul_rn(-0.168736f, r),
                                              __fmul_rn(0.331264f, g)),
                                    __fmul_rn(0.5f, bl)), 128.0f);
    float crv = __fadd_rn(__fsub_rn(__fsub_rn(__fmul_rn(0.5f, r),
                                              __fmul_rn(0.418688f, g)),
                                    __fmul_rn(0.081312f, bl)), 128.0f);
    y  = __fsub_rn(yv, 128.0f);
    cb = __fsub_rn(cbv, 128.0f);
    cr = __fsub_rn(crv, 128.0f);
}

__device__ __forceinline__ void inv_px(float y, float cb, float cr,
                                       float& r, float& g, float& b) {
    float yy  = __fadd_rn(y, 128.0f);
    float cbb = __fsub_rn(__fadd_rn(cb, 128.0f), 128.0f);
    float crr = __fsub_rn(__fadd_rn(cr, 128.0f), 128.0f);
    float rr = __fadd_rn(yy, __fmul_rn(1.402f, crr));
    float gg = __fsub_rn(__fsub_rn(yy, __fmul_rn(0.344136f, cbb)),
                         __fmul_rn(0.714136f, crr));
    float bb = __fadd_rn(yy, __fmul_rn(1.772f, cbb));
    const float inv255 = 1.0f / 255.0f;
    r = __fmul_rn(rintf(fminf(fmaxf(rr, 0.0f), 255.0f)), inv255);
    g = __fmul_rn(rintf(fminf(fmaxf(gg, 0.0f), 255.0f)), inv255);
    b = __fmul_rn(rintf(fminf(fmaxf(bb, 0.0f), 255.0f)), inv255);
}

__global__ void __launch_bounds__(192, 2)
jpeg_kernel(const float* __restrict__ in, const int* __restrict__ qp,
            float* __restrict__ out) {
    extern __shared__ float sm[];
    float2* qtab = (float2*)(sm + 3 * PLANEQ * 4);
    const int t  = threadIdx.x;
    const int by = blockIdx.x;   // block-row (H/8 = 64)
    const int b  = blockIdx.y;   // batch

    // ---- quant tables (lum @ [0..63], chr @ [64..127]) -------------------
    if (t < 128) {
        int qi = qp[0];
        if (qi < 1 || qi > 100) {           // scalar may arrive as float bits
            float f = __int_as_float(qi);
            qi = (int)f;
        }
        if (qi < 1) qi = 1;
        if (qi > 100) qi = 100;
        double scale = (qi < 50) ? 5000.0 / (double)qi : 200.0 - 2.0 * (double)qi;
        double base  = (t < 64) ? (double)LUMT[t] : (double)CHRT[t - 64];
        double v = floor((base * scale + 50.0) / 100.0);
        v = (v < 1.0) ? 1.0 : ((v > 255.0) ? 255.0 : v);
        float qf = (float)v;
        qtab[t] = make_float2(qf, 1.0f / qf);
    }

    const size_t pstride = (size_t)NH * NW;
    const float* pr = in + ((size_t)b * 3 + 0) * pstride + (size_t)by * 8 * NW;
    const float* pg = pr + pstride;
    const float* pb = pg + pstride;

    float4* sY = (float4*)sm;
    float4* sU = sY + PLANEQ;
    float4* sV = sU + PLANEQ;

    // ---- Phase A: load + color fwd -> smem -------------------------------
    for (int i = t; i < 1024; i += 192) {          // 8 rows x 128 quads
        int r = i >> 7, qx = i & 127;
        float4 R4 = *(const float4*)(pr + r * NW + qx * 4);
        float4 G4 = *(const float4*)(pg + r * NW + qx * 4);
        float4 B4 = *(const float4*)(pb + r * NW + qx * 4);
        float4 y4, u4, v4;
        fwd_px(R4.x, G4.x, B4.x, y4.x, u4.x, v4.x);
        fwd_px(R4.y, G4.y, B4.y, y4.y, u4.y, v4.y);
        fwd_px(R4.z, G4.z, B4.z, y4.z, u4.z, v4.z);
        fwd_px(R4.w, G4.w, B4.w, y4.w, u4.w, v4.w);
        int dst = r * QROW + (qx >> 1) + ((qx & 1) ? 68 : 0);
        sY[dst] = y4; sU[dst] = u4; sV[dst] = v4;
    }
    __syncthreads();

    // ---- Phase B: per-thread 8x8 block transform -------------------------
    {
        const int c  = t >> 6;       // 0:Y 1:Cb 2:Cr
        const int bx = t & 63;
        float4* pl = sY + c * PLANEQ;
        float blk[8][8];
        #pragma unroll
        for (int r = 0; r < 8; r++) {
            float4 a  = pl[r * QROW + bx];
            float4 b2 = pl[r * QROW + 68 + bx];
            blk[r][0] = a.x;  blk[r][1] = a.y;  blk[r][2] = a.z;  blk[r][3] = a.w;
            blk[r][4] = b2.x; blk[r][5] = b2.y; blk[r][6] = b2.z; blk[r][7] = b2.w;
        }
        #pragma unroll
        for (int r = 0; r < 8; r++) dct8<1>(&blk[r][0]);
        #pragma unroll
        for (int j = 0; j < 8; j++) dct8<8>(&blk[0][j]);

        const float2* q = qtab + (c ? 64 : 0);
        #pragma unroll
        for (int i = 0; i < 64; i++) {
            float2 qq = q[i];
            float x  = blk[i >> 3][i & 7];
            float yq = __fmul_rn(x, qq.y);
            float rs = fmaf(-qq.x, yq, x);      // Newton step -> correctly
            yq = fmaf(rs, qq.y, yq);            // rounded x / q
            blk[i >> 3][i & 7] = __fmul_rn(rintf(yq), qq.x);
        }

        #pragma unroll
        for (int j = 0; j < 8; j++) idct8<8>(&blk[0][j]);
        #pragma unroll
        for (int r = 0; r < 8; r++) idct8<1>(&blk[r][0]);

        #pragma unroll
        for (int r = 0; r < 8; r++) {
            float4 a  = make_float4(blk[r][0], blk[r][1], blk[r][2], blk[r][3]);
            float4 b2 = make_float4(blk[r][4], blk[r][5], blk[r][6], blk[r][7]);
            pl[r * QROW + bx]      = a;
            pl[r * QROW + 68 + bx] = b2;
        }
    }
    __syncthreads();

    // ---- Phase C: color inv -> store -------------------------------------
    float* orr = out + ((size_t)b * 3 + 0) * pstride + (size_t)by * 8 * NW;
    float* og  = orr + pstride;
    float* ob  = og + pstride;
    for (int i = t; i < 1024; i += 192) {
        int r = i >> 7, qx = i & 127;
        int src = r * QROW + (qx >> 1) + ((qx & 1) ? 68 : 0);
        float4 y4 = sY[src], u4 = sU[src], v4 = sV[src];
        float4 R4, G4, B4;
        inv_px(y4.x, u4.x, v4.x, R4.x, G4.x, B4.x);
        inv_px(y4.y, u4.y, v4.y, R4.y, G4.y, B4.y);
        inv_px(y4.z, u4.z, v4.z, R4.z, G4.z, B4.z);
        inv_px(y4.w, u4.w, v4.w, R4.w, G4.w, B4.w);
        *(float4*)(orr + r * NW + qx * 4) = R4;
        *(float4*)(og  + r * NW + qx * 4) = G4;
        *(float4*)(ob  + r * NW + qx * 4) = B4;
    }
}

extern "C" void kernel_launch(void* const* d_in, const int* in_sizes, int n_in,
                              void* d_out, int out_size) {
    const float* in = (const float*)d_in[0];
    const int*   qp = (const int*)d_in[1];
    float*       out = (float*)d_out;
    (void)in_sizes; (void)n_in; (void)out_size;

    cudaFuncSetAttribute(jpeg_kernel,
                         cudaFuncAttributeMaxDynamicSharedMemorySize, SMEM_BYTES);
    dim3 grid(NH / 8, NB);          // 64 block-rows x 32 images = 2048 CTAs
    jpeg_kernel<<<grid, 192, SMEM_BYTES>>>(in, qp, out);
}